// round 5
// baseline (speedup 1.0000x reference)
#include <cuda_runtime.h>
#include <cuda_fp16.h>
#include <cstdint>

// ---------------------------------------------------------------------------
// S=8 streams, I=64 mod dims, M=256 features, N=16384 batch.
// Collapsed math:  z_g[n,s,m] = sum_i C_g[s,m,i]*mod[n,s,i] + Bias[s,g,m]
//   C_g  = alpha_g * (W_g[:, :M] @ Wx)                       (per stream)
//   Bias = alpha_g * (b_g + W_g[:,:M]@bx + W_g[:,M:]@h0)
//   alpha = -log2(e) for sigmoid gates (i,f,o), +2*log2(e) for tanh gate (g)
// Gates:  sigmoid(z) = rcp(1 + ex2(z'))  ;  tanh(z) = 1 - 2*rcp(1 + ex2(z'))
// Main GEMM per (stream, 64-feature chunk): [128 x 256] = [128 x 64] @ [64 x 256]
// using mma.sync m16n8k16 fp16 (fp32 accum), K=64, no precision split needed.
// ---------------------------------------------------------------------------

#define LOG2E_F 1.4426950408889634f
#define TANHC_SCALE 2.885390081777927f  // 2*log2(e)

// Composed weights, fp16, PRE-SWIZZLED (exact SW128 SMEM image).
// [s][chunk] slab: 256 rows (n = gate*64 + f) x 64 fp16 K-cols (128B rows).
__device__ __align__(16) __half g_B[8 * 4 * 16384];
__device__ float g_Bias[8192];  // [(s*4+g)*256 + m], alpha-folded, gate order i,f,g,o

__device__ __forceinline__ uint32_t smem_u32(const void* p) {
    uint32_t a;
    asm("{ .reg .u64 t; cvta.to.shared.u64 t, %1; cvt.u32.u64 %0, t; }" : "=r"(a) : "l"(p));
    return a;
}
__device__ __forceinline__ float ex2f(float x) { float y; asm("ex2.approx.f32 %0, %1;" : "=f"(y) : "f"(x)); return y; }
__device__ __forceinline__ float rcpf(float x) { float y; asm("rcp.approx.f32 %0, %1;" : "=f"(y) : "f"(x)); return y; }

#define SWZ(off) ((off) ^ (((off) >> 3) & 0x70))

#define LDSM4(r, addr)                                                          \
    asm volatile("ldmatrix.sync.aligned.m8n8.x4.shared.b16 {%0,%1,%2,%3}, [%4];" \
        : "=r"((r)[0]), "=r"((r)[1]), "=r"((r)[2]), "=r"((r)[3]) : "r"(addr))

#define MMA16816(d, a, b0, b1)                                                  \
    asm volatile("mma.sync.aligned.m16n8k16.row.col.f32.f16.f16.f32 "           \
        "{%0,%1,%2,%3}, {%4,%5,%6,%7}, {%8,%9}, {%0,%1,%2,%3};"                 \
        : "+f"((d)[0]), "+f"((d)[1]), "+f"((d)[2]), "+f"((d)[3])                \
        : "r"((a)[0]), "r"((a)[1]), "r"((a)[2]), "r"((a)[3]), "r"(b0), "r"(b1))

// ---------------------------------------------------------------------------
// P1: compose C_g = alpha_g * (W_g[:, :256] @ Wx) for one (s, gate, chunk),
// convert fp16, write pre-swizzled image.  Grid 128 = 8s x 4g x 4chunk.
// ---------------------------------------------------------------------------
__global__ void __launch_bounds__(256) lnlstm_p1(
    const float* __restrict__ Wx, const float* __restrict__ Wi, const float* __restrict__ Wf,
    const float* __restrict__ Wg, const float* __restrict__ Wo)
{
    __shared__ float Wxs[64][65];
    __shared__ float Wgs[64][65];
    int bx = blockIdx.x;
    int s = bx >> 4, g = (bx >> 2) & 3, cch = bx & 3;
    const float* Wgate = (g == 0 ? Wi : g == 1 ? Wf : g == 2 ? Wg : Wo);
    int t = threadIdx.x;
    int i = t & 63, fg = t >> 6;  // i: K-col of C (mod dim), fg: feature group of 16

    float acc[16];
#pragma unroll
    for (int j = 0; j < 16; ++j) acc[j] = 0.f;

    for (int kt = 0; kt < 4; ++kt) {
        __syncthreads();
#pragma unroll
        for (int j = 0; j < 16; ++j) {
            int idx = t + 256 * j;
            int r0 = idx >> 6, c0i = idx & 63;
            Wxs[r0][c0i] = Wx[(size_t)(s * 256 + kt * 64 + r0) * 64 + c0i];
            Wgs[r0][c0i] = Wgate[(size_t)(s * 256 + cch * 64 + r0) * 512 + kt * 64 + c0i];
        }
        __syncthreads();
#pragma unroll 4
        for (int kk = 0; kk < 64; ++kk) {
            float wx = Wxs[kk][i];
#pragma unroll
            for (int jj = 0; jj < 16; ++jj)
                acc[jj] = fmaf(Wgs[fg * 16 + jj][kk], wx, acc[jj]);
        }
    }

    float alpha = (g == 2) ? TANHC_SCALE : -LOG2E_F;
    size_t ibase = (size_t)(s * 4 + cch) * 16384;
#pragma unroll
    for (int jj = 0; jj < 16; ++jj) {
        float v = acc[jj] * alpha;
        int f = fg * 16 + jj;
        int n = g * 64 + f;                            // image row
        uint32_t so = SWZ((uint32_t)(n * 128 + i * 2)); // byte offset, swizzled
        g_B[ibase + (so >> 1)] = __float2half_rn(v);
    }
}

// ---------------------------------------------------------------------------
// P2: biases  Bias[s,g,m] = alpha_g*(b_g + W_g[:,:256]@bx + W_g[:,256:]@h0)
// ---------------------------------------------------------------------------
__global__ void lnlstm_p2(
    const float* __restrict__ Wi, const float* __restrict__ Wf,
    const float* __restrict__ Wg, const float* __restrict__ Wo,
    const float* __restrict__ bi, const float* __restrict__ bff,
    const float* __restrict__ bg, const float* __restrict__ bo,
    const float* __restrict__ bx, const float* __restrict__ h0)
{
    int id = blockIdx.x * blockDim.x + threadIdx.x;
    if (id >= 8192) return;
    int s = id >> 10, g = (id >> 8) & 3, m = id & 255;
    const float* W = (g == 0 ? Wi : g == 1 ? Wf : g == 2 ? Wg : Wo) + (size_t)(s * 256 + m) * 512;
    const float* bb = (g == 0 ? bi : g == 1 ? bff : g == 2 ? bg : bo);
    float acc = bb[s * 256 + m];
#pragma unroll 4
    for (int k = 0; k < 256; ++k) acc = fmaf(W[k], bx[s * 256 + k], acc);
#pragma unroll 4
    for (int k = 0; k < 256; ++k) acc = fmaf(W[256 + k], h0[s * 256 + k], acc);
    float alpha = (g == 2) ? TANHC_SCALE : -LOG2E_F;
    g_Bias[id] = alpha * acc;
}

// ---------------------------------------------------------------------------
// Main kernel: CTA = (128-batch tile, stream s, 64-feature chunk). 256 thr.
// 8 warps: w_m = w>>1 (batch 32-slice), w_f = w&1 (feature 32-half).
// Per warp: 4 gates sequentially, each M=32 x N=32 x K=64 fp16 HMMA.
// SMEM (1024-aligned): bias[256]f32 | c0[64]f32 | A 16KB | B 32KB
// ---------------------------------------------------------------------------
static constexpr unsigned SMEM_BYTES = 2048 + 16384 + 32768 + 1024;

__global__ void __launch_bounds__(256, 2)
lnlstm_main(const float* __restrict__ mod, const float* __restrict__ c0g, float* __restrict__ out)
{
    extern __shared__ char dsm[];
    uint32_t sb = smem_u32(dsm);
    uint32_t ab = (sb + 1023u) & ~1023u;
    char* base = dsm + (ab - sb);

    float* bias_s = (float*)base;            // 1024B
    float* c0_s = (float*)(base + 1024);     // 256B (+768 pad)
    char* Ap = base + 2048;                  // 16KB: [128 rows][128B]
    char* Bp = base + 2048 + 16384;          // 32KB: [256 rows][128B]
    const uint32_t Aa = ab + 2048, Ba = Aa + 16384;

    int tid = threadIdx.x;
    int lane = tid & 31, w = tid >> 5;
    int bx = blockIdx.x;
    int b = bx >> 5, s = (bx >> 2) & 7, cch = bx & 3;
    int n0 = b * 128;
    int mbase = (w >> 1) * 32;
    int fbase = (w & 1) * 32;

    // --- B tile: straight float4 copy of pre-swizzled image ---
    {
        const float4* sB = (const float4*)(g_B + (size_t)(s * 4 + cch) * 16384);
        float4* dB = (float4*)Bp;
#pragma unroll
        for (int j = 0; j < 8; ++j) dB[tid + 256 * j] = sB[tid + 256 * j];
    }
    // --- bias + c0 ---
    bias_s[tid] = g_Bias[(s * 4 + (tid >> 6)) * 256 + cch * 64 + (tid & 63)];
    if (tid < 64) c0_s[tid] = c0g[s * 256 + cch * 64 + tid];

    // --- A tile: fp32 mod -> fp16, swizzled store (128 rows x 64 cols) ---
    {
        const float* mp = mod + (size_t)n0 * 512 + s * 64;
#pragma unroll
        for (int j = 0; j < 8; ++j) {
            int idx = tid + 256 * j;
            int r = idx >> 4, q = idx & 15;
            float4 v = *(const float4*)(mp + (size_t)r * 512 + q * 4);
            __half2 h01 = __floats2half2_rn(v.x, v.y);
            __half2 h23 = __floats2half2_rn(v.z, v.w);
            uint2 pk;
            pk.x = *(uint32_t*)&h01;
            pk.y = *(uint32_t*)&h23;
            uint32_t so = SWZ((uint32_t)(r * 128 + q * 8));
            *(uint2*)(Ap + so) = pk;
        }
    }
    __syncthreads();

    // per-thread ldmatrix row/col pieces
    const int rowA = lane & 15;                       // A: tiles (m0-7,kL)(m8-15,kL)(m0-7,kH)(m8-15,kH)
    const int colA = (lane >> 4) * 16;
    const int rowB = (lane & 7) + ((lane >> 4) << 3); // B: tiles (n0,kL)(n0,kH)(n1,kL)(n1,kH)
    const int colB = ((lane >> 3) & 1) * 16;

    float P[2][4][4];
    float* orow0 = out + (size_t)(n0 + mbase + (lane >> 2)) * 2048 + s * 256 + cch * 64 + fbase + (lane & 3) * 2;

#pragma unroll
    for (int step = 0; step < 4; ++step) {
        const int gsel = (step == 0) ? 0 : (step == 1) ? 2 : (step == 2) ? 1 : 3;  // i, g, f, o

        float acc[2][4][4];
#pragma unroll
        for (int mt = 0; mt < 2; ++mt)
#pragma unroll
            for (int nt = 0; nt < 4; ++nt)
#pragma unroll
                for (int q = 0; q < 4; ++q) acc[mt][nt][q] = 0.f;

#pragma unroll
        for (int ks = 0; ks < 4; ++ks) {
            uint32_t a[2][4];
#pragma unroll
            for (int mt = 0; mt < 2; ++mt) {
                uint32_t addr = Aa + SWZ((uint32_t)((mbase + mt * 16 + rowA) * 128 + ks * 32 + colA));
                LDSM4(a[mt], addr);
            }
#pragma unroll
            for (int ntp = 0; ntp < 2; ++ntp) {
                uint32_t bfr[4];
                uint32_t addr = Ba + SWZ((uint32_t)((gsel * 64 + fbase + ntp * 16 + rowB) * 128 + ks * 32 + colB));
                LDSM4(bfr, addr);
                MMA16816(acc[0][2 * ntp + 0], a[0], bfr[0], bfr[1]);
                MMA16816(acc[0][2 * ntp + 1], a[0], bfr[2], bfr[3]);
                MMA16816(acc[1][2 * ntp + 0], a[1], bfr[0], bfr[1]);
                MMA16816(acc[1][2 * ntp + 1], a[1], bfr[2], bfr[3]);
            }
        }

        // gate bias (per thread: 2 consecutive f per n-tile)
        float2 bias2[4];
#pragma unroll
        for (int nt = 0; nt < 4; ++nt)
            bias2[nt] = *(float2*)&bias_s[gsel * 64 + fbase + nt * 8 + (lane & 3) * 2];

#pragma unroll
        for (int mt = 0; mt < 2; ++mt) {
#pragma unroll
            for (int nt = 0; nt < 4; ++nt) {
#pragma unroll
                for (int q = 0; q < 4; ++q) {
                    float z = acc[mt][nt][q] + ((q & 1) ? bias2[nt].y : bias2[nt].x);
                    if (step == 0) {                    // i-gate: P = sigmoid
                        P[mt][nt][q] = rcpf(1.f + ex2f(z));
                    } else if (step == 1) {             // g-gate: P *= tanh
                        P[mt][nt][q] *= 1.f - 2.f * rcpf(1.f + ex2f(z));
                    } else if (step == 2) {             // f-gate: P += sigmoid * c0
                        float2 c02 = *(float2*)&c0_s[fbase + nt * 8 + (lane & 3) * 2];
                        float c0v = (q & 1) ? c02.y : c02.x;
                        P[mt][nt][q] = fmaf(rcpf(1.f + ex2f(z)), c0v, P[mt][nt][q]);
                    } else {                            // o-gate: h = sigmoid * tanh(c)
                        float so = rcpf(1.f + ex2f(z));
                        float tc = 1.f - 2.f * rcpf(1.f + ex2f(TANHC_SCALE * P[mt][nt][q]));
                        P[mt][nt][q] = so * tc;
                    }
                }
            }
        }
    }

    // --- stores: per (mt, nt): 2 float2 rows (q0q1 at m, q2q3 at m+8) ---
#pragma unroll
    for (int mt = 0; mt < 2; ++mt) {
#pragma unroll
        for (int nt = 0; nt < 4; ++nt) {
            float* p0 = orow0 + (size_t)(mt * 16) * 2048 + nt * 8;
            *(float2*)p0 = make_float2(P[mt][nt][0], P[mt][nt][1]);
            *(float2*)(p0 + (size_t)8 * 2048) = make_float2(P[mt][nt][2], P[mt][nt][3]);
        }
    }
}

// ---------------------------------------------------------------------------
extern "C" void kernel_launch(void* const* d_in, const int* in_sizes, int n_in,
                              void* d_out, int out_size)
{
    const float* mod = (const float*)d_in[0];
    const float* h0  = (const float*)d_in[1];
    const float* c0  = (const float*)d_in[2];
    const float* Wx  = (const float*)d_in[3];
    const float* bxp = (const float*)d_in[4];
    const float* Wi  = (const float*)d_in[5];
    const float* bi  = (const float*)d_in[6];
    const float* Wf  = (const float*)d_in[7];
    const float* bfp = (const float*)d_in[8];
    const float* Wg  = (const float*)d_in[9];
    const float* bg  = (const float*)d_in[10];
    const float* Wo  = (const float*)d_in[11];
    const float* bo  = (const float*)d_in[12];
    float* out = (float*)d_out;

    cudaFuncSetAttribute(lnlstm_main, cudaFuncAttributeMaxDynamicSharedMemorySize, SMEM_BYTES);

    lnlstm_p1<<<128, 256>>>(Wx, Wi, Wf, Wg, Wo);
    lnlstm_p2<<<32, 256>>>(Wi, Wf, Wg, Wo, bi, bfp, bg, bo, bxp, h0);
    lnlstm_main<<<4096, 256, SMEM_BYTES>>>(mod, c0, out);
}

// round 6
// speedup vs baseline: 1.8600x; 1.8600x over previous
#include <cuda_runtime.h>
#include <cuda_fp16.h>
#include <cstdint>

// ---------------------------------------------------------------------------
// S=8 streams, I=64 mod dims, M=256 features, N=16384 batch.
// Collapsed math:  z_g[n,s,m] = sum_i C_g[s,m,i]*mod[n,s,i] + Bias[s,g,m]
//   C_g  = alpha_g * (W_g[:, :M] @ Wx)                       (per stream)
//   Bias = alpha_g * (b_g + W_g[:,:M]@bx + W_g[:,M:]@h0)
//   alpha = 0.5 for sigmoid gates (i,f,o)  [sigma(z) = 0.5*tanh(z/2)+0.5]
//   alpha = 1.0 for tanh gate (g)
// Gate nonlinearities via single-MUFU tanh.approx.f32.
// Main GEMM per (stream, 64-feature chunk): [128 x 256] = [128 x 64] @ [64 x 256]
// with mma.sync m16n8k16 fp16 (fp32 accum), K=64.
// ---------------------------------------------------------------------------

// Composed weights, fp16, PRE-SWIZZLED (exact SW128 SMEM image).
// [s][chunk] slab: 256 rows (n = gate*64 + f) x 64 fp16 K-cols (128B rows).
__device__ __align__(16) __half g_B[8 * 4 * 16384];
__device__ float g_Bias[8192];  // [(s*4+g)*256 + m], alpha-folded, gate order i,f,g,o

__device__ __forceinline__ uint32_t smem_u32(const void* p) {
    uint32_t a;
    asm("{ .reg .u64 t; cvta.to.shared.u64 t, %1; cvt.u32.u64 %0, t; }" : "=r"(a) : "l"(p));
    return a;
}
__device__ __forceinline__ float tanha(float x) {
    float y; asm("tanh.approx.f32 %0, %1;" : "=f"(y) : "f"(x)); return y;
}

#define SWZ(off) ((off) ^ (((off) >> 3) & 0x70))

#define LDSM4(r, addr)                                                          \
    asm volatile("ldmatrix.sync.aligned.m8n8.x4.shared.b16 {%0,%1,%2,%3}, [%4];" \
        : "=r"((r)[0]), "=r"((r)[1]), "=r"((r)[2]), "=r"((r)[3]) : "r"(addr))

#define MMA16816(d, a, b0, b1)                                                  \
    asm volatile("mma.sync.aligned.m16n8k16.row.col.f32.f16.f16.f32 "           \
        "{%0,%1,%2,%3}, {%4,%5,%6,%7}, {%8,%9}, {%0,%1,%2,%3};"                 \
        : "+f"((d)[0]), "+f"((d)[1]), "+f"((d)[2]), "+f"((d)[3])                \
        : "r"((a)[0]), "r"((a)[1]), "r"((a)[2]), "r"((a)[3]), "r"(b0), "r"(b1))

// ---------------------------------------------------------------------------
// Fused precompute: blocks [0,128) compose C_g (one per (s,g,chunk));
// blocks [128,1152) compute biases (one warp per output).
// ---------------------------------------------------------------------------
__global__ void __launch_bounds__(256) lnlstm_pre(
    const float* __restrict__ Wx,
    const float* __restrict__ Wi, const float* __restrict__ Wf,
    const float* __restrict__ Wg, const float* __restrict__ Wo,
    const float* __restrict__ bi, const float* __restrict__ bff,
    const float* __restrict__ bg, const float* __restrict__ bo,
    const float* __restrict__ bx, const float* __restrict__ h0)
{
    __shared__ float Wgs[64][68];
    __shared__ float Wxs[64][68];
    int bxid = blockIdx.x;
    int t = threadIdx.x;

    if (bxid < 128) {
        // ---- weight composition: C = alpha * (Wg[:, cch*64..][0:256] @ Wx) ----
        int s = bxid >> 4, g = (bxid >> 2) & 3, cch = bxid & 3;
        const float* Wgate = (g == 0 ? Wi : g == 1 ? Wf : g == 2 ? Wg : Wo);
        int mg = t >> 4, ig = t & 15;  // thread tile: m rows mg*4..+3, i cols ig*4..+3

        float acc[16];
#pragma unroll
        for (int j = 0; j < 16; ++j) acc[j] = 0.f;

        for (int kt = 0; kt < 4; ++kt) {
            __syncthreads();
#pragma unroll
            for (int jj = 0; jj < 4; ++jj) {
                int idx4 = t + 256 * jj;
                int row = idx4 >> 4, c4 = (idx4 & 15) * 4;
                *(float4*)&Wgs[row][c4] =
                    *(const float4*)&Wgate[(size_t)(s * 256 + cch * 64 + row) * 512 + kt * 64 + c4];
                *(float4*)&Wxs[row][c4] =
                    *(const float4*)&Wx[(size_t)(s * 256 + kt * 64 + row) * 64 + c4];
            }
            __syncthreads();
#pragma unroll 4
            for (int kk = 0; kk < 64; ++kk) {
                float4 wx = *(float4*)&Wxs[kk][ig * 4];
                float w0 = Wgs[mg * 4 + 0][kk];
                float w1 = Wgs[mg * 4 + 1][kk];
                float w2 = Wgs[mg * 4 + 2][kk];
                float w3 = Wgs[mg * 4 + 3][kk];
                acc[0] = fmaf(w0, wx.x, acc[0]);  acc[1] = fmaf(w0, wx.y, acc[1]);
                acc[2] = fmaf(w0, wx.z, acc[2]);  acc[3] = fmaf(w0, wx.w, acc[3]);
                acc[4] = fmaf(w1, wx.x, acc[4]);  acc[5] = fmaf(w1, wx.y, acc[5]);
                acc[6] = fmaf(w1, wx.z, acc[6]);  acc[7] = fmaf(w1, wx.w, acc[7]);
                acc[8] = fmaf(w2, wx.x, acc[8]);  acc[9] = fmaf(w2, wx.y, acc[9]);
                acc[10] = fmaf(w2, wx.z, acc[10]); acc[11] = fmaf(w2, wx.w, acc[11]);
                acc[12] = fmaf(w3, wx.x, acc[12]); acc[13] = fmaf(w3, wx.y, acc[13]);
                acc[14] = fmaf(w3, wx.z, acc[14]); acc[15] = fmaf(w3, wx.w, acc[15]);
            }
        }

        float alpha = (g == 2) ? 1.0f : 0.5f;
        size_t ibase = (size_t)(s * 4 + cch) * 16384;
#pragma unroll
        for (int r = 0; r < 4; ++r) {
            int n = g * 64 + mg * 4 + r;  // image row
#pragma unroll
            for (int cp = 0; cp < 2; ++cp) {
                int i = ig * 4 + cp * 2;
                __half2 h2 = __floats2half2_rn(acc[r * 4 + cp * 2] * alpha,
                                               acc[r * 4 + cp * 2 + 1] * alpha);
                uint32_t so = SWZ((uint32_t)(n * 128 + i * 2));
                *(__half2*)&g_B[ibase + (so >> 1)] = h2;
            }
        }
    } else {
        // ---- bias: one warp per output (coalesced float4 dot over K=512) ----
        int wid = t >> 5, lane = t & 31;
        int id = (bxid - 128) * 8 + wid;  // < 8192
        int s = id >> 10, g = (id >> 8) & 3, m = id & 255;
        const float* W = (g == 0 ? Wi : g == 1 ? Wf : g == 2 ? Wg : Wo)
                         + (size_t)(s * 256 + m) * 512;
        const float* bb = (g == 0 ? bi : g == 1 ? bff : g == 2 ? bg : bo);
        float acc = 0.f;
#pragma unroll
        for (int it = 0; it < 4; ++it) {
            int k0 = it * 128 + lane * 4;
            float4 w = *(const float4*)&W[k0];
            float4 x = (it < 2) ? *(const float4*)&bx[s * 256 + k0]
                                : *(const float4*)&h0[s * 256 + k0 - 256];
            acc += w.x * x.x + w.y * x.y + w.z * x.z + w.w * x.w;
        }
#pragma unroll
        for (int d = 16; d > 0; d >>= 1)
            acc += __shfl_xor_sync(0xFFFFFFFFu, acc, d);
        if (lane == 0) {
            float alpha = (g == 2) ? 1.0f : 0.5f;
            g_Bias[id] = alpha * (bb[s * 256 + m] + acc);
        }
    }
}

// ---------------------------------------------------------------------------
// Main kernel: CTA = (128-batch tile, stream s, 64-feature chunk). 256 thr.
// 8 warps: w>>1 = batch 32-slice, w&1 = feature 32-half.
// A fragments preloaded once per warp; 4 gates sequentially (M32 x N32 x K64).
// SMEM (1024-aligned): bias[256]f32 | c0[64]f32 | A 16KB | B 32KB
// ---------------------------------------------------------------------------
static constexpr unsigned SMEM_BYTES = 2048 + 16384 + 32768 + 1024;

__global__ void __launch_bounds__(256, 2)
lnlstm_main(const float* __restrict__ mod, const float* __restrict__ c0g, float* __restrict__ out)
{
    extern __shared__ char dsm[];
    uint32_t sb = smem_u32(dsm);
    uint32_t ab = (sb + 1023u) & ~1023u;
    char* base = dsm + (ab - sb);

    float* bias_s = (float*)base;            // 1024B
    float* c0_s = (float*)(base + 1024);     // 256B (+768 pad)
    char* Ap = base + 2048;                  // 16KB: [128 rows][128B]
    char* Bp = base + 2048 + 16384;          // 32KB: [256 rows][128B]
    const uint32_t Aa = ab + 2048, Ba = Aa + 16384;

    int tid = threadIdx.x;
    int lane = tid & 31, w = tid >> 5;
    int bx = blockIdx.x;
    int b = bx >> 5, s = (bx >> 2) & 7, cch = bx & 3;
    int n0 = b * 128;
    int mbase = (w >> 1) * 32;
    int fbase = (w & 1) * 32;

    // --- B tile: straight float4 copy of pre-swizzled image ---
    {
        const float4* sB = (const float4*)(g_B + (size_t)(s * 4 + cch) * 16384);
        float4* dB = (float4*)Bp;
#pragma unroll
        for (int j = 0; j < 8; ++j) dB[tid + 256 * j] = sB[tid + 256 * j];
    }
    // --- bias + c0 ---
    bias_s[tid] = g_Bias[(s * 4 + (tid >> 6)) * 256 + cch * 64 + (tid & 63)];
    if (tid < 64) c0_s[tid] = c0g[s * 256 + cch * 64 + tid];

    // --- A tile: fp32 mod -> fp16, swizzled store (128 rows x 64 cols) ---
    {
        const float* mp = mod + (size_t)n0 * 512 + s * 64;
#pragma unroll
        for (int j = 0; j < 8; ++j) {
            int idx = tid + 256 * j;
            int r = idx >> 4, q = idx & 15;
            float4 v = *(const float4*)(mp + (size_t)r * 512 + q * 4);
            __half2 h01 = __floats2half2_rn(v.x, v.y);
            __half2 h23 = __floats2half2_rn(v.z, v.w);
            uint2 pk;
            pk.x = *(uint32_t*)&h01;
            pk.y = *(uint32_t*)&h23;
            uint32_t so = SWZ((uint32_t)(r * 128 + q * 8));
            *(uint2*)(Ap + so) = pk;
        }
    }
    __syncthreads();

    // per-thread ldmatrix row/col pieces
    const int rowA = lane & 15;                       // A tiles: (m0-7,kL)(m8-15,kL)(m0-7,kH)(m8-15,kH)
    const int colA = (lane >> 4) * 16;
    const int rowB = (lane & 7) + ((lane >> 4) << 3); // B tiles: (n0,kL)(n0,kH)(n1,kL)(n1,kH)
    const int colB = ((lane >> 3) & 1) * 16;

    // --- preload ALL A fragments (reused across the 4 gates) ---
    uint32_t afr[4][2][4];
#pragma unroll
    for (int ks = 0; ks < 4; ++ks)
#pragma unroll
        for (int mt = 0; mt < 2; ++mt) {
            uint32_t addr = Aa + SWZ((uint32_t)((mbase + mt * 16 + rowA) * 128 + ks * 32 + colA));
            LDSM4(afr[ks][mt], addr);
        }

    float P[2][4][4];
    float* orow0 = out + (size_t)(n0 + mbase + (lane >> 2)) * 2048 + s * 256 + cch * 64 + fbase + (lane & 3) * 2;

#pragma unroll
    for (int step = 0; step < 4; ++step) {
        const int gsel = (step == 0) ? 0 : (step == 1) ? 2 : (step == 2) ? 1 : 3;  // i, g, f, o

        float acc[2][4][4];
#pragma unroll
        for (int mt = 0; mt < 2; ++mt)
#pragma unroll
            for (int nt = 0; nt < 4; ++nt)
#pragma unroll
                for (int q = 0; q < 4; ++q) acc[mt][nt][q] = 0.f;

#pragma unroll
        for (int ks = 0; ks < 4; ++ks) {
#pragma unroll
            for (int ntp = 0; ntp < 2; ++ntp) {
                uint32_t bfr[4];
                uint32_t addr = Ba + SWZ((uint32_t)((gsel * 64 + fbase + ntp * 16 + rowB) * 128 + ks * 32 + colB));
                LDSM4(bfr, addr);
                MMA16816(acc[0][2 * ntp + 0], afr[ks][0], bfr[0], bfr[1]);
                MMA16816(acc[0][2 * ntp + 1], afr[ks][0], bfr[2], bfr[3]);
                MMA16816(acc[1][2 * ntp + 0], afr[ks][1], bfr[0], bfr[1]);
                MMA16816(acc[1][2 * ntp + 1], afr[ks][1], bfr[2], bfr[3]);
            }
        }

        // gate bias (per thread: 2 consecutive f per n-tile)
        float2 bias2[4];
#pragma unroll
        for (int nt = 0; nt < 4; ++nt)
            bias2[nt] = *(float2*)&bias_s[gsel * 64 + fbase + nt * 8 + (lane & 3) * 2];

#pragma unroll
        for (int mt = 0; mt < 2; ++mt) {
#pragma unroll
            for (int nt = 0; nt < 4; ++nt) {
#pragma unroll
                for (int q = 0; q < 4; ++q) {
                    float z = acc[mt][nt][q] + ((q & 1) ? bias2[nt].y : bias2[nt].x);
                    float tz = tanha(z);
                    if (step == 0) {                    // i-gate: P = sigmoid
                        P[mt][nt][q] = fmaf(tz, 0.5f, 0.5f);
                    } else if (step == 1) {             // g-gate: P *= tanh
                        P[mt][nt][q] *= tz;
                    } else if (step == 2) {             // f-gate: P += sigmoid * c0
                        float2 c02 = *(float2*)&c0_s[fbase + nt * 8 + (lane & 3) * 2];
                        float c0v = (q & 1) ? c02.y : c02.x;
                        P[mt][nt][q] = fmaf(fmaf(tz, 0.5f, 0.5f), c0v, P[mt][nt][q]);
                    } else {                            // o-gate: h = sigmoid * tanh(c)
                        float so = fmaf(tz, 0.5f, 0.5f);
                        P[mt][nt][q] = so * tanha(P[mt][nt][q]);
                    }
                }
            }
        }
    }

    // --- stores: per (mt, nt): 2 float2 rows (q0q1 at m, q2q3 at m+8) ---
#pragma unroll
    for (int mt = 0; mt < 2; ++mt) {
#pragma unroll
        for (int nt = 0; nt < 4; ++nt) {
            float* p0 = orow0 + (size_t)(mt * 16) * 2048 + nt * 8;
            *(float2*)p0 = make_float2(P[mt][nt][0], P[mt][nt][1]);
            *(float2*)(p0 + (size_t)8 * 2048) = make_float2(P[mt][nt][2], P[mt][nt][3]);
        }
    }
}

// ---------------------------------------------------------------------------
extern "C" void kernel_launch(void* const* d_in, const int* in_sizes, int n_in,
                              void* d_out, int out_size)
{
    const float* mod = (const float*)d_in[0];
    const float* h0  = (const float*)d_in[1];
    const float* c0  = (const float*)d_in[2];
    const float* Wx  = (const float*)d_in[3];
    const float* bxp = (const float*)d_in[4];
    const float* Wi  = (const float*)d_in[5];
    const float* bi  = (const float*)d_in[6];
    const float* Wf  = (const float*)d_in[7];
    const float* bfp = (const float*)d_in[8];
    const float* Wg  = (const float*)d_in[9];
    const float* bg  = (const float*)d_in[10];
    const float* Wo  = (const float*)d_in[11];
    const float* bo  = (const float*)d_in[12];
    float* out = (float*)d_out;

    cudaFuncSetAttribute(lnlstm_main, cudaFuncAttributeMaxDynamicSharedMemorySize, SMEM_BYTES);

    lnlstm_pre<<<1152, 256>>>(Wx, Wi, Wf, Wg, Wo, bi, bfp, bg, bo, bxp, h0);
    lnlstm_main<<<4096, 256, SMEM_BYTES>>>(mod, c0, out);
}

// round 7
// speedup vs baseline: 2.0401x; 1.0968x over previous
#include <cuda_runtime.h>
#include <cuda_fp16.h>
#include <cstdint>

// ---------------------------------------------------------------------------
// S=8 streams, I=64 mod dims, M=256 features, N=16384 batch.
// Collapsed math:  z_g[n,s,m] = sum_i C_g[s,m,i]*mod[n,s,i] + Bias[s,g,m]
//   C_g  = alpha_g * (W_g[:, :M] @ Wx)                       (per stream)
//   Bias = alpha_g * (b_g + W_g[:,:M]@bx + W_g[:,M:]@h0)
//   alpha = 0.5 for sigmoid gates (i,f,o)  [sigma(z) = 0.5*tanh(z/2)+0.5]
//   alpha = 1.0 for tanh gate (g)
// Gate nonlinearities via single-MUFU tanh.approx.f32.
// Main: CTA = (128-batch, stream); loops 4 feature chunks; per chunk a
// [128 x 256] = [128 x 64] @ [64 x 256] fp16 mma.sync GEMM (fp32 accum).
// ---------------------------------------------------------------------------

// Composed weights, fp16, PRE-SWIZZLED (exact SW128 SMEM image).
// [s][chunk] slab: 256 rows (n = gate*64 + f) x 64 fp16 K-cols (128B rows).
__device__ __align__(16) __half g_B[8 * 4 * 16384];
__device__ float g_Bias[8192];  // [(s*4+g)*256 + m], alpha-folded, gate order i,f,g,o

__device__ __forceinline__ uint32_t smem_u32(const void* p) {
    uint32_t a;
    asm("{ .reg .u64 t; cvta.to.shared.u64 t, %1; cvt.u32.u64 %0, t; }" : "=r"(a) : "l"(p));
    return a;
}
__device__ __forceinline__ float tanha(float x) {
    float y; asm("tanh.approx.f32 %0, %1;" : "=f"(y) : "f"(x)); return y;
}

#define SWZ(off) ((off) ^ (((off) >> 3) & 0x70))

#define LDSM4(r, addr)                                                          \
    asm volatile("ldmatrix.sync.aligned.m8n8.x4.shared.b16 {%0,%1,%2,%3}, [%4];" \
        : "=r"((r)[0]), "=r"((r)[1]), "=r"((r)[2]), "=r"((r)[3]) : "r"(addr))

#define MMA16816(d, a, b0, b1)                                                  \
    asm volatile("mma.sync.aligned.m16n8k16.row.col.f32.f16.f16.f32 "           \
        "{%0,%1,%2,%3}, {%4,%5,%6,%7}, {%8,%9}, {%0,%1,%2,%3};"                 \
        : "+f"((d)[0]), "+f"((d)[1]), "+f"((d)[2]), "+f"((d)[3])                \
        : "r"((a)[0]), "r"((a)[1]), "r"((a)[2]), "r"((a)[3]), "r"(b0), "r"(b1))

#define CPA_COMMIT() asm volatile("cp.async.commit_group;" ::: "memory")

// ---------------------------------------------------------------------------
// Precompute.  Blocks [0,256): weight composition, one per (s,g,cch,ihalf):
// 64 m-rows x 32 i-cols of C, K=256.  Blocks [256,2304): biases, 4 warps each.
// ---------------------------------------------------------------------------
__global__ void __launch_bounds__(128) lnlstm_pre(
    const float* __restrict__ Wx,
    const float* __restrict__ Wi, const float* __restrict__ Wf,
    const float* __restrict__ Wg, const float* __restrict__ Wo,
    const float* __restrict__ bi, const float* __restrict__ bff,
    const float* __restrict__ bg, const float* __restrict__ bo,
    const float* __restrict__ bx, const float* __restrict__ h0)
{
    __shared__ float WgT[64][68];   // [kk][m]  (transposed W_gate slice)
    __shared__ float Wxs[64][36];   // [kk][i_local]
    int bxid = blockIdx.x;
    int t = threadIdx.x;

    if (bxid < 256) {
        int s = bxid >> 5, g = (bxid >> 3) & 3, cch = (bxid >> 1) & 3, ih = bxid & 1;
        const float* Wgate = (g == 0 ? Wi : g == 1 ? Wf : g == 2 ? Wg : Wo);
        int mg = t >> 3, ig = t & 7;  // thread tile: m = mg*4..+3, i_local = ig*4..+3

        float acc[16];
#pragma unroll
        for (int j = 0; j < 16; ++j) acc[j] = 0.f;

        for (int kt = 0; kt < 4; ++kt) {
            __syncthreads();
#pragma unroll
            for (int jj = 0; jj < 8; ++jj) {           // W_gate slice, transposed
                int idx = t + 128 * jj;
                int m = idx >> 4, kc = (idx & 15) * 4;
                float4 w = *(const float4*)&Wgate[(size_t)(s * 256 + cch * 64 + m) * 512 + kt * 64 + kc];
                WgT[kc + 0][m] = w.x; WgT[kc + 1][m] = w.y;
                WgT[kc + 2][m] = w.z; WgT[kc + 3][m] = w.w;
            }
#pragma unroll
            for (int jj = 0; jj < 4; ++jj) {           // Wx slice (this i-half)
                int idx = t + 128 * jj;
                int kk = idx >> 3, ic = (idx & 7) * 4;
                *(float4*)&Wxs[kk][ic] =
                    *(const float4*)&Wx[(size_t)(s * 256 + kt * 64 + kk) * 64 + ih * 32 + ic];
            }
            __syncthreads();
#pragma unroll 4
            for (int kk = 0; kk < 64; ++kk) {
                float4 wm = *(float4*)&WgT[kk][mg * 4];
                float4 wi = *(float4*)&Wxs[kk][ig * 4];
                acc[0]  = fmaf(wm.x, wi.x, acc[0]);  acc[1]  = fmaf(wm.x, wi.y, acc[1]);
                acc[2]  = fmaf(wm.x, wi.z, acc[2]);  acc[3]  = fmaf(wm.x, wi.w, acc[3]);
                acc[4]  = fmaf(wm.y, wi.x, acc[4]);  acc[5]  = fmaf(wm.y, wi.y, acc[5]);
                acc[6]  = fmaf(wm.y, wi.z, acc[6]);  acc[7]  = fmaf(wm.y, wi.w, acc[7]);
                acc[8]  = fmaf(wm.z, wi.x, acc[8]);  acc[9]  = fmaf(wm.z, wi.y, acc[9]);
                acc[10] = fmaf(wm.z, wi.z, acc[10]); acc[11] = fmaf(wm.z, wi.w, acc[11]);
                acc[12] = fmaf(wm.w, wi.x, acc[12]); acc[13] = fmaf(wm.w, wi.y, acc[13]);
                acc[14] = fmaf(wm.w, wi.z, acc[14]); acc[15] = fmaf(wm.w, wi.w, acc[15]);
            }
        }

        float alpha = (g == 2) ? 1.0f : 0.5f;
        size_t ibase = (size_t)(s * 4 + cch) * 16384;
#pragma unroll
        for (int r = 0; r < 4; ++r) {
            int n = g * 64 + mg * 4 + r;  // image row
#pragma unroll
            for (int cp = 0; cp < 2; ++cp) {
                int i = ih * 32 + ig * 4 + cp * 2;
                __half2 h2 = __floats2half2_rn(acc[r * 4 + cp * 2] * alpha,
                                               acc[r * 4 + cp * 2 + 1] * alpha);
                uint32_t so = SWZ((uint32_t)(n * 128 + i * 2));
                *(__half2*)&g_B[ibase + (so >> 1)] = h2;
            }
        }
    } else {
        // ---- bias: one warp per output (coalesced float4 dot over K=512) ----
        int wid = t >> 5, lane = t & 31;
        int id = (bxid - 256) * 4 + wid;  // < 8192
        int s = id >> 10, g = (id >> 8) & 3, m = id & 255;
        const float* W = (g == 0 ? Wi : g == 1 ? Wf : g == 2 ? Wg : Wo)
                         + (size_t)(s * 256 + m) * 512;
        const float* bb = (g == 0 ? bi : g == 1 ? bff : g == 2 ? bg : bo);
        float acc = 0.f;
#pragma unroll
        for (int it = 0; it < 4; ++it) {
            int k0 = it * 128 + lane * 4;
            float4 w = *(const float4*)&W[k0];
            float4 x = (it < 2) ? *(const float4*)&bx[s * 256 + k0]
                                : *(const float4*)&h0[s * 256 + k0 - 256];
            acc += w.x * x.x + w.y * x.y + w.z * x.z + w.w * x.w;
        }
#pragma unroll
        for (int d = 16; d > 0; d >>= 1)
            acc += __shfl_xor_sync(0xFFFFFFFFu, acc, d);
        if (lane == 0) {
            float alpha = (g == 2) ? 1.0f : 0.5f;
            g_Bias[id] = alpha * (bb[s * 256 + m] + acc);
        }
    }
}

// ---------------------------------------------------------------------------
// Main kernel: CTA = (128-batch tile, stream).  256 thr, 8 warps (4m x 2f).
// A tile built + fragments preloaded ONCE; 4 feature chunks streamed with
// double-buffered cp.async of pre-swizzled B images.
// SMEM (1024-aligned): bias[1024] | c0[256] | pad | A 16KB | B0 32KB | B1 32KB
// ---------------------------------------------------------------------------
static constexpr unsigned SMEM_BYTES = 90112 + 1024;

__device__ __forceinline__ void prefetch_B(uint32_t dstA, const __half* slab, int tid) {
#pragma unroll
    for (int j = 0; j < 8; ++j) {
        uint32_t d = dstA + tid * 16 + j * 4096;
        const char* sp = (const char*)slab + tid * 16 + j * 4096;
        asm volatile("cp.async.cg.shared.global [%0], [%1], 16;" :: "r"(d), "l"(sp));
    }
    CPA_COMMIT();
}

__global__ void __launch_bounds__(256, 2)
lnlstm_main(const float* __restrict__ mod, const float* __restrict__ c0g, float* __restrict__ out)
{
    extern __shared__ char dsm[];
    uint32_t sb = smem_u32(dsm);
    uint32_t ab = (sb + 1023u) & ~1023u;
    char* base = dsm + (ab - sb);

    float* bias_s = (float*)base;            // 4KB: [g*256 + m]
    float* c0_s = (float*)(base + 4096);     // 1KB
    char* Ap = base + 8192;                  // 16KB: [128 rows][128B]
    const uint32_t Aa = ab + 8192;
    const uint32_t Ba0 = Aa + 16384, Ba1 = Ba0 + 32768;

    int tid = threadIdx.x;
    int lane = tid & 31, w = tid >> 5;
    int bx = blockIdx.x;
    int s = bx >> 7, b = bx & 127;
    int n0 = b * 128;
    int mbase = (w >> 1) * 32;
    int fbase = (w & 1) * 32;

    const __half* slab = g_B + (size_t)s * 4 * 16384;
    prefetch_B(Ba0, slab, tid);
    prefetch_B(Ba1, slab + 16384, tid);

    // --- bias + c0 ---
#pragma unroll
    for (int j = 0; j < 4; ++j) bias_s[tid + 256 * j] = g_Bias[s * 1024 + tid + 256 * j];
    c0_s[tid] = c0g[s * 256 + tid];

    // --- A tile: fp32 mod -> fp16, swizzled store (128 rows x 64 cols) ---
    {
        const float* mp = mod + (size_t)n0 * 512 + s * 64;
#pragma unroll
        for (int j = 0; j < 8; ++j) {
            int idx = tid + 256 * j;
            int r = idx >> 4, q = idx & 15;
            float4 v = *(const float4*)(mp + (size_t)r * 512 + q * 4);
            __half2 h01 = __floats2half2_rn(v.x, v.y);
            __half2 h23 = __floats2half2_rn(v.z, v.w);
            uint2 pk;
            pk.x = *(uint32_t*)&h01;
            pk.y = *(uint32_t*)&h23;
            uint32_t so = SWZ((uint32_t)(r * 128 + q * 8));
            *(uint2*)(Ap + so) = pk;
        }
    }
    __syncthreads();

    // per-thread ldmatrix row/col pieces
    const int rowA = lane & 15;                       // A tiles: (m0-7,kL)(m8-15,kL)(m0-7,kH)(m8-15,kH)
    const int colA = (lane >> 4) * 16;
    const int rowB = (lane & 7) + ((lane >> 4) << 3); // B tiles: (n0,kL)(n0,kH)(n1,kL)(n1,kH)
    const int colB = ((lane >> 3) & 1) * 16;

    // --- preload ALL A fragments (reused across chunks AND gates) ---
    uint32_t afr[4][2][4];
#pragma unroll
    for (int ks = 0; ks < 4; ++ks)
#pragma unroll
        for (int mt = 0; mt < 2; ++mt) {
            uint32_t addr = Aa + SWZ((uint32_t)((mbase + mt * 16 + rowA) * 128 + ks * 32 + colA));
            LDSM4(afr[ks][mt], addr);
        }

    for (int cch = 0; cch < 4; ++cch) {
        if (cch == 3) asm volatile("cp.async.wait_group 0;" ::: "memory");
        else         asm volatile("cp.async.wait_group 1;" ::: "memory");
        __syncthreads();
        const uint32_t Bcur = (cch & 1) ? Ba1 : Ba0;

        float P[2][4][4];
        float* orow0 = out + (size_t)(n0 + mbase + (lane >> 2)) * 2048
                       + s * 256 + cch * 64 + fbase + (lane & 3) * 2;

#pragma unroll
        for (int step = 0; step < 4; ++step) {
            const int gsel = (step == 0) ? 0 : (step == 1) ? 2 : (step == 2) ? 1 : 3;  // i,g,f,o

            float acc[2][4][4];
#pragma unroll
            for (int mt = 0; mt < 2; ++mt)
#pragma unroll
                for (int nt = 0; nt < 4; ++nt)
#pragma unroll
                    for (int q = 0; q < 4; ++q) acc[mt][nt][q] = 0.f;

#pragma unroll
            for (int ks = 0; ks < 4; ++ks) {
#pragma unroll
                for (int ntp = 0; ntp < 2; ++ntp) {
                    uint32_t bfr[4];
                    uint32_t addr = Bcur + SWZ((uint32_t)((gsel * 64 + fbase + ntp * 16 + rowB) * 128 + ks * 32 + colB));
                    LDSM4(bfr, addr);
                    MMA16816(acc[0][2 * ntp + 0], afr[ks][0], bfr[0], bfr[1]);
                    MMA16816(acc[0][2 * ntp + 1], afr[ks][0], bfr[2], bfr[3]);
                    MMA16816(acc[1][2 * ntp + 0], afr[ks][1], bfr[0], bfr[1]);
                    MMA16816(acc[1][2 * ntp + 1], afr[ks][1], bfr[2], bfr[3]);
                }
            }

            float2 bias2[4];
#pragma unroll
            for (int nt = 0; nt < 4; ++nt)
                bias2[nt] = *(float2*)&bias_s[gsel * 256 + cch * 64 + fbase + nt * 8 + (lane & 3) * 2];

#pragma unroll
            for (int mt = 0; mt < 2; ++mt) {
#pragma unroll
                for (int nt = 0; nt < 4; ++nt) {
#pragma unroll
                    for (int q = 0; q < 4; ++q) {
                        float z = acc[mt][nt][q] + ((q & 1) ? bias2[nt].y : bias2[nt].x);
                        float tz = tanha(z);
                        if (step == 0) {                    // i: P = sigmoid
                            P[mt][nt][q] = fmaf(tz, 0.5f, 0.5f);
                        } else if (step == 1) {             // g: P *= tanh
                            P[mt][nt][q] *= tz;
                        } else if (step == 2) {             // f: P += sigmoid * c0
                            float2 c02 = *(float2*)&c0_s[cch * 64 + fbase + nt * 8 + (lane & 3) * 2];
                            float c0v = (q & 1) ? c02.y : c02.x;
                            P[mt][nt][q] = fmaf(fmaf(tz, 0.5f, 0.5f), c0v, P[mt][nt][q]);
                        } else {                            // o: h = sigmoid * tanh(c)
                            float so = fmaf(tz, 0.5f, 0.5f);
                            P[mt][nt][q] = so * tanha(P[mt][nt][q]);
                        }
                    }
                }
            }
        }

        // --- stores ---
#pragma unroll
        for (int mt = 0; mt < 2; ++mt) {
#pragma unroll
            for (int nt = 0; nt < 4; ++nt) {
                float* p0 = orow0 + (size_t)(mt * 16) * 2048 + nt * 8;
                *(float2*)p0 = make_float2(P[mt][nt][0], P[mt][nt][1]);
                *(float2*)(p0 + (size_t)8 * 2048) = make_float2(P[mt][nt][2], P[mt][nt][3]);
            }
        }

        __syncthreads();   // all warps done with Bcur before overwrite
        if (cch < 2) prefetch_B(Bcur, slab + (cch + 2) * 16384, tid);
    }
}

// ---------------------------------------------------------------------------
extern "C" void kernel_launch(void* const* d_in, const int* in_sizes, int n_in,
                              void* d_out, int out_size)
{
    const float* mod = (const float*)d_in[0];
    const float* h0  = (const float*)d_in[1];
    const float* c0  = (const float*)d_in[2];
    const float* Wx  = (const float*)d_in[3];
    const float* bxp = (const float*)d_in[4];
    const float* Wi  = (const float*)d_in[5];
    const float* bi  = (const float*)d_in[6];
    const float* Wf  = (const float*)d_in[7];
    const float* bfp = (const float*)d_in[8];
    const float* Wg  = (const float*)d_in[9];
    const float* bg  = (const float*)d_in[10];
    const float* Wo  = (const float*)d_in[11];
    const float* bo  = (const float*)d_in[12];
    float* out = (float*)d_out;

    cudaFuncSetAttribute(lnlstm_main, cudaFuncAttributeMaxDynamicSharedMemorySize, SMEM_BYTES);

    lnlstm_pre<<<2304, 128>>>(Wx, Wi, Wf, Wg, Wo, bi, bfp, bg, bo, bxp, h0);
    lnlstm_main<<<1024, 256, SMEM_BYTES>>>(mod, c0, out);
}

// round 8
// speedup vs baseline: 2.6289x; 1.2886x over previous
#include <cuda_runtime.h>
#include <cuda_fp16.h>
#include <cstdint>

// ---------------------------------------------------------------------------
// S=8 streams, I=64 mod dims, M=256 features, N=16384 batch.
// Collapsed math:  z_g[n,s,m] = sum_i C_g[s,m,i]*mod[n,s,i] + Bias[s,g,m]
//   C_g  = alpha_g * (W_g[:, :M] @ Wx)                       (per stream)
//   Bias = alpha_g * (b_g + W_g[:,:M]@bx + W_g[:,M:]@h0)
//   alpha = 0.5 for sigmoid gates (i,f,o)  [sigma(z) = 0.5*tanh(z/2)+0.5]
//   alpha = 1.0 for tanh gate (g)
// Gate nonlinearities via single-MUFU tanh.approx.f32.
// f-gate (and its GEMM) is skipped per 64-feature chunk when c0 chunk == 0
// (exact: f*0 == 0 in the reference too).
// ---------------------------------------------------------------------------

// Composed weights, fp16, PRE-SWIZZLED (exact SW128 SMEM image).
// [s][chunk] slab: 256 rows (n = gate*64 + f) x 64 fp16 K-cols (128B rows).
__device__ __align__(16) __half g_B[8 * 4 * 16384];
__device__ float g_Bias[8192];  // [(s*4+g)*256 + m], alpha-folded, gate order i,f,g,o

__device__ __forceinline__ uint32_t smem_u32(const void* p) {
    uint32_t a;
    asm("{ .reg .u64 t; cvta.to.shared.u64 t, %1; cvt.u32.u64 %0, t; }" : "=r"(a) : "l"(p));
    return a;
}
__device__ __forceinline__ float tanha(float x) {
    float y; asm("tanh.approx.f32 %0, %1;" : "=f"(y) : "f"(x)); return y;
}

#define SWZ(off) ((off) ^ (((off) >> 3) & 0x70))

#define LDSM4(r, addr)                                                          \
    asm volatile("ldmatrix.sync.aligned.m8n8.x4.shared.b16 {%0,%1,%2,%3}, [%4];" \
        : "=r"((r)[0]), "=r"((r)[1]), "=r"((r)[2]), "=r"((r)[3]) : "r"(addr))

#define MMA16816(d, a, b0, b1)                                                  \
    asm volatile("mma.sync.aligned.m16n8k16.row.col.f32.f16.f16.f32 "           \
        "{%0,%1,%2,%3}, {%4,%5,%6,%7}, {%8,%9}, {%0,%1,%2,%3};"                 \
        : "+f"((d)[0]), "+f"((d)[1]), "+f"((d)[2]), "+f"((d)[3])                \
        : "r"((a)[0]), "r"((a)[1]), "r"((a)[2]), "r"((a)[3]), "r"(b0), "r"(b1))

#define CPA_COMMIT() asm volatile("cp.async.commit_group;" ::: "memory")

// ---------------------------------------------------------------------------
// Precompute.  Blocks [0,512): weight composition, one per (s,g,cch,mh,ih):
// 32 m-rows x 32 i-cols of C, K=256.  Blocks [512,2560): biases, 4 warps each.
// ---------------------------------------------------------------------------
__global__ void __launch_bounds__(128) lnlstm_pre(
    const float* __restrict__ Wx,
    const float* __restrict__ Wi, const float* __restrict__ Wf,
    const float* __restrict__ Wg, const float* __restrict__ Wo,
    const float* __restrict__ bi, const float* __restrict__ bff,
    const float* __restrict__ bg, const float* __restrict__ bo,
    const float* __restrict__ bx, const float* __restrict__ h0)
{
    __shared__ float Wgs[32][68];   // [m_local][kk]   natural layout
    __shared__ float Wxs[64][36];   // [kk][i_local]
    int bxid = blockIdx.x;
    int t = threadIdx.x;

    if (bxid < 512) {
        int s = bxid >> 6, g = (bxid >> 4) & 3, cch = (bxid >> 2) & 3;
        int mh = (bxid >> 1) & 1, ih = bxid & 1;
        const float* Wgate = (g == 0 ? Wi : g == 1 ? Wf : g == 2 ? Wg : Wo);
        int mg = t >> 4, ig = t & 15;  // thread tile: m = mg*4..+3 (of 32), i = ig*2..+1 (of 32)

        float acc[8];
#pragma unroll
        for (int j = 0; j < 8; ++j) acc[j] = 0.f;

        for (int kt = 0; kt < 4; ++kt) {
            __syncthreads();
#pragma unroll
            for (int jj = 0; jj < 4; ++jj) {           // Wg slice 32 x 64, natural
                int idx = t + 128 * jj;
                int m = idx >> 4, kc = (idx & 15) * 4;
                *(float4*)&Wgs[m][kc] =
                    *(const float4*)&Wgate[(size_t)(s * 256 + cch * 64 + mh * 32 + m) * 512 + kt * 64 + kc];
            }
#pragma unroll
            for (int jj = 0; jj < 4; ++jj) {           // Wx slice 64 x 32
                int idx = t + 128 * jj;
                int kk = idx >> 3, ic = (idx & 7) * 4;
                *(float4*)&Wxs[kk][ic] =
                    *(const float4*)&Wx[(size_t)(s * 256 + kt * 64 + kk) * 64 + ih * 32 + ic];
            }
            __syncthreads();
#pragma unroll 4
            for (int kk = 0; kk < 64; ++kk) {
                float w0 = Wgs[mg * 4 + 0][kk];        // broadcast reads
                float w1 = Wgs[mg * 4 + 1][kk];
                float w2 = Wgs[mg * 4 + 2][kk];
                float w3 = Wgs[mg * 4 + 3][kk];
                float2 wi = *(float2*)&Wxs[kk][ig * 2];
                acc[0] = fmaf(w0, wi.x, acc[0]);  acc[1] = fmaf(w0, wi.y, acc[1]);
                acc[2] = fmaf(w1, wi.x, acc[2]);  acc[3] = fmaf(w1, wi.y, acc[3]);
                acc[4] = fmaf(w2, wi.x, acc[4]);  acc[5] = fmaf(w2, wi.y, acc[5]);
                acc[6] = fmaf(w3, wi.x, acc[6]);  acc[7] = fmaf(w3, wi.y, acc[7]);
            }
        }

        float alpha = (g == 2) ? 1.0f : 0.5f;
        size_t ibase = (size_t)(s * 4 + cch) * 16384;
#pragma unroll
        for (int r = 0; r < 4; ++r) {
            int n = g * 64 + mh * 32 + mg * 4 + r;     // image row
            int i = ih * 32 + ig * 2;
            __half2 h2 = __floats2half2_rn(acc[r * 2] * alpha, acc[r * 2 + 1] * alpha);
            uint32_t so = SWZ((uint32_t)(n * 128 + i * 2));
            *(__half2*)&g_B[ibase + (so >> 1)] = h2;
        }
    } else {
        // ---- bias: one warp per output (coalesced float4 dot over K=512) ----
        int wid = t >> 5, lane = t & 31;
        int id = (bxid - 512) * 4 + wid;  // < 8192
        int s = id >> 10, g = (id >> 8) & 3, m = id & 255;
        const float* W = (g == 0 ? Wi : g == 1 ? Wf : g == 2 ? Wg : Wo)
                         + (size_t)(s * 256 + m) * 512;
        const float* bb = (g == 0 ? bi : g == 1 ? bff : g == 2 ? bg : bo);
        float acc = 0.f;
#pragma unroll
        for (int it = 0; it < 4; ++it) {
            int k0 = it * 128 + lane * 4;
            float4 w = *(const float4*)&W[k0];
            float4 x = (it < 2) ? *(const float4*)&bx[s * 256 + k0]
                                : *(const float4*)&h0[s * 256 + k0 - 256];
            acc += w.x * x.x + w.y * x.y + w.z * x.z + w.w * x.w;
        }
#pragma unroll
        for (int d = 16; d > 0; d >>= 1)
            acc += __shfl_xor_sync(0xFFFFFFFFu, acc, d);
        if (lane == 0) {
            float alpha = (g == 2) ? 1.0f : 0.5f;
            g_Bias[id] = alpha * (bb[s * 256 + m] + acc);
        }
    }
}

// ---------------------------------------------------------------------------
// Main kernel: CTA = (128-batch tile, stream).  256 thr, 8 warps (4m x 2f).
// A tile built + fragments preloaded ONCE; 4 feature chunks streamed with
// double-buffered cp.async of pre-swizzled B images.  f-gate skipped per
// chunk when c0 chunk is all zero.
// SMEM (1024-aligned): bias 4KB | c0 1KB | flags | A 16KB | B0 32KB | B1 32KB
// ---------------------------------------------------------------------------
static constexpr unsigned SMEM_BYTES = 90112 + 1024;

__device__ __forceinline__ void prefetch_B(uint32_t dstA, const __half* slab, int tid) {
#pragma unroll
    for (int j = 0; j < 8; ++j) {
        uint32_t d = dstA + tid * 16 + j * 4096;
        const char* sp = (const char*)slab + tid * 16 + j * 4096;
        asm volatile("cp.async.cg.shared.global [%0], [%1], 16;" :: "r"(d), "l"(sp));
    }
    CPA_COMMIT();
}

__global__ void __launch_bounds__(256, 2)
lnlstm_main(const float* __restrict__ mod, const float* __restrict__ c0g, float* __restrict__ out)
{
    extern __shared__ char dsm[];
    uint32_t sb = smem_u32(dsm);
    uint32_t ab = (sb + 1023u) & ~1023u;
    char* base = dsm + (ab - sb);

    float* bias_s = (float*)base;            // 4KB: [g*256 + cch*64 + f]
    float* c0_s = (float*)(base + 4096);     // 1KB
    int* c0nz = (int*)(base + 5120);         // 4 flags
    char* Ap = base + 8192;                  // 16KB: [128 rows][128B]
    const uint32_t Aa = ab + 8192;
    const uint32_t Ba0 = Aa + 16384, Ba1 = Ba0 + 32768;

    int tid = threadIdx.x;
    int lane = tid & 31, w = tid >> 5;
    int bx = blockIdx.x;
    int s = bx >> 7, b = bx & 127;
    int n0 = b * 128;
    int mbase = (w >> 1) * 32;
    int fbase = (w & 1) * 32;

    const __half* slab = g_B + (size_t)s * 4 * 16384;
    prefetch_B(Ba0, slab, tid);
    prefetch_B(Ba1, slab + 16384, tid);

    if (tid < 4) c0nz[tid] = 0;

    // --- bias + c0 + per-chunk nonzero flags ---
#pragma unroll
    for (int j = 0; j < 4; ++j) bias_s[tid + 256 * j] = g_Bias[s * 1024 + tid + 256 * j];
    {
        float cv = c0g[s * 256 + tid];
        c0_s[tid] = cv;
        if (cv != 0.0f) atomicOr(&c0nz[tid >> 6], 1);
    }

    // --- A tile: fp32 mod -> fp16, swizzled store (128 rows x 64 cols) ---
    {
        const float* mp = mod + (size_t)n0 * 512 + s * 64;
#pragma unroll
        for (int j = 0; j < 8; ++j) {
            int idx = tid + 256 * j;
            int r = idx >> 4, q = idx & 15;
            float4 v = *(const float4*)(mp + (size_t)r * 512 + q * 4);
            __half2 h01 = __floats2half2_rn(v.x, v.y);
            __half2 h23 = __floats2half2_rn(v.z, v.w);
            uint2 pk;
            pk.x = *(uint32_t*)&h01;
            pk.y = *(uint32_t*)&h23;
            uint32_t so = SWZ((uint32_t)(r * 128 + q * 8));
            *(uint2*)(Ap + so) = pk;
        }
    }
    __syncthreads();

    // per-thread ldmatrix row/col pieces
    const int rowA = lane & 15;                       // A tiles: (m0-7,kL)(m8-15,kL)(m0-7,kH)(m8-15,kH)
    const int colA = (lane >> 4) * 16;
    const int rowB = (lane & 7) + ((lane >> 4) << 3); // B tiles: (n0,kL)(n0,kH)(n1,kL)(n1,kH)
    const int colB = ((lane >> 3) & 1) * 16;

    // --- preload ALL A fragments (reused across chunks AND gates) ---
    uint32_t afr[4][2][4];
#pragma unroll
    for (int ks = 0; ks < 4; ++ks)
#pragma unroll
        for (int mt = 0; mt < 2; ++mt) {
            uint32_t addr = Aa + SWZ((uint32_t)((mbase + mt * 16 + rowA) * 128 + ks * 32 + colA));
            LDSM4(afr[ks][mt], addr);
        }

    for (int cch = 0; cch < 4; ++cch) {
        if (cch == 3) asm volatile("cp.async.wait_group 0;" ::: "memory");
        else         asm volatile("cp.async.wait_group 1;" ::: "memory");
        __syncthreads();
        const uint32_t Bcur = (cch & 1) ? Ba1 : Ba0;
        const int fgate_on = c0nz[cch];

        float P[2][4][4];
        float* orow0 = out + (size_t)(n0 + mbase + (lane >> 2)) * 2048
                       + s * 256 + cch * 64 + fbase + (lane & 3) * 2;

#pragma unroll
        for (int step = 0; step < 4; ++step) {
            const int gsel = (step == 0) ? 0 : (step == 1) ? 2 : (step == 2) ? 1 : 3;  // i,g,f,o
            if (step == 2 && !fgate_on) continue;      // f*c0 == 0 exactly

            // acc init = bias (mma accumulates on top)
            float2 bias2[4];
#pragma unroll
            for (int nt = 0; nt < 4; ++nt)
                bias2[nt] = *(float2*)&bias_s[gsel * 256 + cch * 64 + fbase + nt * 8 + (lane & 3) * 2];

            float acc[2][4][4];
#pragma unroll
            for (int mt = 0; mt < 2; ++mt)
#pragma unroll
                for (int nt = 0; nt < 4; ++nt) {
                    acc[mt][nt][0] = bias2[nt].x; acc[mt][nt][1] = bias2[nt].y;
                    acc[mt][nt][2] = bias2[nt].x; acc[mt][nt][3] = bias2[nt].y;
                }

#pragma unroll
            for (int ks = 0; ks < 4; ++ks) {
#pragma unroll
                for (int ntp = 0; ntp < 2; ++ntp) {
                    uint32_t bfr[4];
                    uint32_t addr = Bcur + SWZ((uint32_t)((gsel * 64 + fbase + ntp * 16 + rowB) * 128 + ks * 32 + colB));
                    LDSM4(bfr, addr);
                    MMA16816(acc[0][2 * ntp + 0], afr[ks][0], bfr[0], bfr[1]);
                    MMA16816(acc[0][2 * ntp + 1], afr[ks][0], bfr[2], bfr[3]);
                    MMA16816(acc[1][2 * ntp + 0], afr[ks][1], bfr[0], bfr[1]);
                    MMA16816(acc[1][2 * ntp + 1], afr[ks][1], bfr[2], bfr[3]);
                }
            }

#pragma unroll
            for (int mt = 0; mt < 2; ++mt) {
#pragma unroll
                for (int nt = 0; nt < 4; ++nt) {
#pragma unroll
                    for (int q = 0; q < 4; ++q) {
                        float tz = tanha(acc[mt][nt][q]);
                        if (step == 0) {                    // i: P = sigmoid
                            P[mt][nt][q] = fmaf(tz, 0.5f, 0.5f);
                        } else if (step == 1) {             // g: P *= tanh
                            P[mt][nt][q] *= tz;
                        } else if (step == 2) {             // f: P += sigmoid * c0
                            float2 c02 = *(float2*)&c0_s[cch * 64 + fbase + nt * 8 + (lane & 3) * 2];
                            float c0v = (q & 1) ? c02.y : c02.x;
                            P[mt][nt][q] = fmaf(fmaf(tz, 0.5f, 0.5f), c0v, P[mt][nt][q]);
                        } else {                            // o: h = sigmoid * tanh(c)
                            float so = fmaf(tz, 0.5f, 0.5f);
                            P[mt][nt][q] = so * tanha(P[mt][nt][q]);
                        }
                    }
                }
            }
        }

        // --- stores ---
#pragma unroll
        for (int mt = 0; mt < 2; ++mt) {
#pragma unroll
            for (int nt = 0; nt < 4; ++nt) {
                float* p0 = orow0 + (size_t)(mt * 16) * 2048 + nt * 8;
                *(float2*)p0 = make_float2(P[mt][nt][0], P[mt][nt][1]);
                *(float2*)(p0 + (size_t)8 * 2048) = make_float2(P[mt][nt][2], P[mt][nt][3]);
            }
        }

        __syncthreads();   // all warps done with Bcur before overwrite
        if (cch < 2) prefetch_B(Bcur, slab + (cch + 2) * 16384, tid);
    }
}

// ---------------------------------------------------------------------------
extern "C" void kernel_launch(void* const* d_in, const int* in_sizes, int n_in,
                              void* d_out, int out_size)
{
    const float* mod = (const float*)d_in[0];
    const float* h0  = (const float*)d_in[1];
    const float* c0  = (const float*)d_in[2];
    const float* Wx  = (const float*)d_in[3];
    const float* bxp = (const float*)d_in[4];
    const float* Wi  = (const float*)d_in[5];
    const float* bi  = (const float*)d_in[6];
    const float* Wf  = (const float*)d_in[7];
    const float* bfp = (const float*)d_in[8];
    const float* Wg  = (const float*)d_in[9];
    const float* bg  = (const float*)d_in[10];
    const float* Wo  = (const float*)d_in[11];
    const float* bo  = (const float*)d_in[12];
    float* out = (float*)d_out;

    cudaFuncSetAttribute(lnlstm_main, cudaFuncAttributeMaxDynamicSharedMemorySize, SMEM_BYTES);

    lnlstm_pre<<<2560, 128>>>(Wx, Wi, Wf, Wg, Wo, bi, bfp, bg, bo, bxp, h0);
    lnlstm_main<<<1024, 256, SMEM_BYTES>>>(mod, c0, out);
}